// round 13
// baseline (speedup 1.0000x reference)
#include <cuda_runtime.h>
#include <cuda_bf16.h>
#include <cstdint>
#include <math.h>

#define D  1024
#define T  2048
#define V  32000
#define NB 128     // persistent CTAs, 1 per SM (128 <= 148)
#define JT 8       // hidden units owned per CTA (NB*JT == D)

// ---------------- device scratch (no allocs allowed) ----------------
__device__ __align__(16) float g_xpre[(size_t)T * 4 * D];    // 32 MB x-contrib + bias
// tagged hidden state, double-buffered by step parity: {tag:32 | h_bits:32}
__device__ __align__(16) unsigned long long g_hpk[2][D];
__device__ __align__(16) __nv_bfloat16 g_Hbf[(size_t)T * D]; // 4 MB bf16 hidden states
__device__ __align__(16) __nv_bfloat16 g_Wbf[(size_t)V * D]; // 64 MB bf16 linear weight

// fast sigmoid / tanh via ex2.approx + rcp.approx (rel err ~1e-6)
__device__ __forceinline__ float fast_sigmoid(float x) {
    return __fdividef(1.f, 1.f + __expf(-x));
}
__device__ __forceinline__ float fast_tanh(float x) {
    return fmaf(2.f, __fdividef(1.f, 1.f + __expf(-2.f * x)), -1.f);
}

// ---------------- kernel 1: gather x-projections, reset state ----------------
__global__ void __launch_bounds__(256) gather_kernel(
    const int* __restrict__ X32,
    const float* __restrict__ Wxf, const float* __restrict__ Wxi,
    const float* __restrict__ Wxc, const float* __restrict__ Wxo,
    const float* __restrict__ bf,  const float* __restrict__ bi,
    const float* __restrict__ bc,  const float* __restrict__ bo)
{
    int t   = blockIdx.x;
    int tid = threadIdx.x;

    // int64 vs int32 ids: little-endian int64 ids < 32000 -> odd words zero.
    int pred = 0;
    if (tid < 64) {
        int p = (tid * 37) & 1023;
        pred = (X32[2 * p + 1] != 0);
    }
    int any_nonzero = __syncthreads_or(pred);
    int id = any_nonzero ? X32[t] : X32[2 * t];

    if (t == 0) {
        // h^0 = 0 with tag 0 in slot 0; slot 1 tag 0 (!= any wanted odd tag)
        #pragma unroll
        for (int q = 0; q < 4; ++q) {
            g_hpk[0][tid * 4 + q] = 0ull;
            g_hpk[1][tid * 4 + q] = 0ull;
        }
    }

    const float* Wx[4] = {Wxf, Wxi, Wxc, Wxo};
    const float* bs[4] = {bf,  bi,  bc,  bo};
    size_t rowoff = (size_t)id * D;
    int j = tid * 4;
    #pragma unroll
    for (int g = 0; g < 4; ++g) {
        float4 v = *(const float4*)(Wx[g] + rowoff + j);
        float4 b = *(const float4*)(bs[g] + j);
        v.x += b.x; v.y += b.y; v.z += b.z; v.w += b.w;
        *(float4*)(g_xpre + ((size_t)t * 4 + g) * D + j) = v;
    }
}

// ---------------- kernel 1b: convert linear_weight to bf16 ----------------
__global__ void __launch_bounds__(256) cvt_kernel(const float* __restrict__ W)
{
    size_t i = (size_t)blockIdx.x * 256 + threadIdx.x;   // float4 index
    float4 v = ((const float4*)W)[i];
    __nv_bfloat162* o = (__nv_bfloat162*)g_Wbf + i * 2;
    o[0] = __floats2bfloat162_rn(v.x, v.y);
    o[1] = __floats2bfloat162_rn(v.z, v.w);
}

// ---------------- kernel 2: persistent LSTM, weights in registers ----------
// 128 CTAs x 256 threads, 1 CTA/SM. Thread (warp w, lane) holds
// W[gate(lane>>3)][k in 128w..128(w+1))][j = 8*cta + (lane&7)] in 128 regs.
// Sync: tagged 8B words {step+1, h_bits}; each warp polls exactly its own
// k-segment (warp-local exchange -> __syncwarp, no CTA barrier before FMA).
__global__ void __launch_bounds__(256, 1) lstm_kernel(
    const float* __restrict__ Whf, const float* __restrict__ Whi,
    const float* __restrict__ Whc, const float* __restrict__ Who,
    float* __restrict__ hid_out)
{
    __shared__ float sh_h[D];
    __shared__ float sh_ps[8][33];

    int tid   = threadIdx.x;
    int w     = tid >> 5;
    int lane  = tid & 31;
    int g     = lane >> 3;
    int jj    = lane & 7;
    int jbase = blockIdx.x * JT;
    int j     = jbase + jj;

    const float* Wm = (g == 0) ? Whf : (g == 1) ? Whi : (g == 2) ? Whc : Who;
    float wreg[128];
    #pragma unroll
    for (int kk = 0; kk < 128; ++kk)
        wreg[kk] = Wm[(size_t)(w * 128 + kk) * D + j];

    float c = 0.f;   // cell state: lives in warp-0 lanes 0..7

    for (int t = 0; t < T; ++t) {
        // x-contribution (DRAM streaming; issued early, consumed after reduce)
        float xv = 0.f;
        if (w == 0) xv = __ldcs(&g_xpre[((size_t)t * 4 + g) * D + j]);

        // acquire h^t: poll own 4 tagged words with two 16B volatile loads
        {
            const unsigned long long* hp = &g_hpk[t & 1][tid * 4];
            unsigned tag = (unsigned)t;
            unsigned long long v0, v1, v2, v3;
            for (;;) {
                asm volatile("ld.volatile.global.v2.u64 {%0,%1}, [%2];"
                             : "=l"(v0), "=l"(v1) : "l"(hp));
                asm volatile("ld.volatile.global.v2.u64 {%0,%1}, [%2];"
                             : "=l"(v2), "=l"(v3) : "l"(hp + 2));
                if ((unsigned)(v0 >> 32) == tag && (unsigned)(v1 >> 32) == tag &&
                    (unsigned)(v2 >> 32) == tag && (unsigned)(v3 >> 32) == tag)
                    break;
            }
            ((float4*)sh_h)[tid] = make_float4(
                __uint_as_float((unsigned)v0), __uint_as_float((unsigned)v1),
                __uint_as_float((unsigned)v2), __uint_as_float((unsigned)v3));
        }
        __syncwarp();     // sh_h exchange is warp-local (thread tid's words
                          // tid*4.. lie exactly in warp w's k-segment)

        float a0 = 0.f, a1 = 0.f, a2 = 0.f, a3 = 0.f;
        const float4* h4 = ((const float4*)sh_h) + w * 32;
        #pragma unroll
        for (int q = 0; q < 32; ++q) {
            float4 hv = h4[q];
            a0 = fmaf(hv.x, wreg[4 * q + 0], a0);
            a1 = fmaf(hv.y, wreg[4 * q + 1], a1);
            a2 = fmaf(hv.z, wreg[4 * q + 2], a2);
            a3 = fmaf(hv.w, wreg[4 * q + 3], a3);
        }
        sh_ps[w][lane] = (a0 + a1) + (a2 + a3);
        __syncthreads();   // (B) sh_ps complete

        if (w == 0) {
            float s = xv +
                ((sh_ps[0][lane] + sh_ps[1][lane]) +
                 (sh_ps[2][lane] + sh_ps[3][lane])) +
                ((sh_ps[4][lane] + sh_ps[5][lane]) +
                 (sh_ps[6][lane] + sh_ps[7][lane]));
            float a = (g == 2) ? fast_tanh(s) : fast_sigmoid(s);
            float fv = __shfl_sync(0xffffffffu, a, jj);
            float iv = __shfl_sync(0xffffffffu, a, 8 + jj);
            float gv = __shfl_sync(0xffffffffu, a, 16 + jj);
            float ov = __shfl_sync(0xffffffffu, a, 24 + jj);
            if (lane < 8) {
                c = fmaf(fv, c, iv * gv);
                float h = fast_tanh(c) * ov;
                // publish FIRST: single aligned 8B store = atomic, self-flagging
                unsigned long long pk =
                    ((unsigned long long)(unsigned)(t + 1) << 32) |
                    (unsigned long long)__float_as_uint(h);
                *(volatile unsigned long long*)&g_hpk[(t + 1) & 1][jbase + lane] = pk;
                // off critical path:
                hid_out[(size_t)t * D + jbase + lane] = h;
                g_Hbf[(size_t)t * D + jbase + lane] = __float2bfloat16(h);
            }
        }
        // no trailing sync: sh_ps writes of step t+1 are ordered by the poll
        // (own CTA publishes t+1 only after warp 0 read sh_ps@t), and sync (B)
        // of t+1 orders them before warp 0's next read.
    }
}

// ---------------- kernel 3: bf16 tensor-core GEMM  C = H @ W^T + bias ----------
// 128x128 block tile, BK=32, 8 warps (2x4), 64x32 warp tile, mma.m16n8k16.bf16.
__global__ void __launch_bounds__(256) gemm_kernel(
    const float* __restrict__ bias,   // (V)
    float* __restrict__ out)          // (T, V)
{
    __shared__ __align__(16) __nv_bfloat16 As[2][128][40];
    __shared__ __align__(16) __nv_bfloat16 Bs[2][128][40];

    int tid  = threadIdx.x;
    int lane = tid & 31;
    int w    = tid >> 5;
    int wm   = w >> 2;
    int wn   = w & 3;
    int t0   = blockIdx.y * 128;
    int v0   = blockIdx.x * 128;

    const __nv_bfloat16* Hbf = g_Hbf;
    const __nv_bfloat16* Wbf = g_Wbf;

    float acc[4][4][4];
    #pragma unroll
    for (int mi = 0; mi < 4; ++mi)
        #pragma unroll
        for (int ni = 0; ni < 4; ++ni)
            #pragma unroll
            for (int q = 0; q < 4; ++q) acc[mi][ni][q] = 0.f;

    #pragma unroll
    for (int s = 0; s < 2; ++s) {
        int f = tid + s * 256, row = f >> 2, q = f & 3;
        *(uint4*)&As[0][row][q * 8] =
            *(const uint4*)(Hbf + (size_t)(t0 + row) * D + q * 8);
        *(uint4*)&Bs[0][row][q * 8] =
            *(const uint4*)(Wbf + (size_t)(v0 + row) * D + q * 8);
    }
    __syncthreads();

    int p = 0;
    for (int kb = 0; kb < 32; ++kb) {
        uint4 ra[2], rb[2];
        if (kb < 31) {
            int d0 = (kb + 1) * 32;
            #pragma unroll
            for (int s = 0; s < 2; ++s) {
                int f = tid + s * 256, row = f >> 2, q = f & 3;
                ra[s] = *(const uint4*)(Hbf + (size_t)(t0 + row) * D + d0 + q * 8);
                rb[s] = *(const uint4*)(Wbf + (size_t)(v0 + row) * D + d0 + q * 8);
            }
        }

        #pragma unroll
        for (int ks = 0; ks < 2; ++ks) {
            int k0 = ks * 16;
            uint32_t af[4][4];
            #pragma unroll
            for (int mi = 0; mi < 4; ++mi) {
                int row = wm * 64 + mi * 16 + (lane & 7) + ((lane >> 3) & 1) * 8;
                int kc  = k0 + (lane >> 4) * 8;
                uint32_t a = (uint32_t)__cvta_generic_to_shared(&As[p][row][kc]);
                asm volatile(
                    "ldmatrix.sync.aligned.m8n8.x4.shared.b16 {%0,%1,%2,%3}, [%4];"
                    : "=r"(af[mi][0]), "=r"(af[mi][1]),
                      "=r"(af[mi][2]), "=r"(af[mi][3]) : "r"(a));
            }
            uint32_t bfr[4][2];
            #pragma unroll
            for (int ni = 0; ni < 4; ++ni) {
                int nrow = wn * 32 + ni * 8 + (lane & 7);
                int kc   = k0 + ((lane >> 3) & 1) * 8;
                uint32_t a = (uint32_t)__cvta_generic_to_shared(&Bs[p][nrow][kc]);
                asm volatile(
                    "ldmatrix.sync.aligned.m8n8.x2.shared.b16 {%0,%1}, [%2];"
                    : "=r"(bfr[ni][0]), "=r"(bfr[ni][1]) : "r"(a));
            }
            #pragma unroll
            for (int mi = 0; mi < 4; ++mi)
                #pragma unroll
                for (int ni = 0; ni < 4; ++ni)
                    asm volatile(
                        "mma.sync.aligned.m16n8k16.row.col.f32.bf16.bf16.f32 "
                        "{%0,%1,%2,%3}, {%4,%5,%6,%7}, {%8,%9}, {%0,%1,%2,%3};"
                        : "+f"(acc[mi][ni][0]), "+f"(acc[mi][ni][1]),
                          "+f"(acc[mi][ni][2]), "+f"(acc[mi][ni][3])
                        : "r"(af[mi][0]), "r"(af[mi][1]),
                          "r"(af[mi][2]), "r"(af[mi][3]),
                          "r"(bfr[ni][0]), "r"(bfr[ni][1]));
        }

        if (kb < 31) {
            #pragma unroll
            for (int s = 0; s < 2; ++s) {
                int f = tid + s * 256, row = f >> 2, q = f & 3;
                *(uint4*)&As[p ^ 1][row][q * 8] = ra[s];
                *(uint4*)&Bs[p ^ 1][row][q * 8] = rb[s];
            }
        }
        __syncthreads();
        p ^= 1;
    }

    int rowA = lane >> 2;
    int colB = (lane & 3) * 2;
    #pragma unroll
    for (int mi = 0; mi < 4; ++mi) {
        int m = t0 + wm * 64 + mi * 16 + rowA;
        #pragma unroll
        for (int ni = 0; ni < 4; ++ni) {
            int n = v0 + wn * 32 + ni * 8 + colB;
            float bx = bias[n], by = bias[n + 1];
            *(float2*)(out + (size_t)m * V + n) =
                make_float2(acc[mi][ni][0] + bx, acc[mi][ni][1] + by);
            *(float2*)(out + (size_t)(m + 8) * V + n) =
                make_float2(acc[mi][ni][2] + bx, acc[mi][ni][3] + by);
        }
    }
}

// ---------------- kernel 4: online single-read log_softmax ----------------
__global__ void __launch_bounds__(256) logsoftmax_kernel(float* __restrict__ out)
{
    size_t t   = blockIdx.x;
    float* row = out + t * (size_t)V;
    int tid = threadIdx.x;
    __shared__ float sm[8], ss[8];

    float m = -INFINITY, s = 0.f;
    const float4* r4 = (const float4*)row;
    for (int i = tid; i < V / 4; i += 256) {
        float4 v = r4[i];
        float mx = fmaxf(fmaxf(v.x, v.y), fmaxf(v.z, v.w));
        if (mx > m) { s *= expf(m - mx); m = mx; }
        s += expf(v.x - m) + expf(v.y - m) + expf(v.z - m) + expf(v.w - m);
    }
    #pragma unroll
    for (int o = 16; o; o >>= 1) {
        float mo = __shfl_xor_sync(0xffffffffu, m, o);
        float so = __shfl_xor_sync(0xffffffffu, s, o);
        float mn = fmaxf(m, mo);
        s = s * expf(m - mn) + so * expf(mo - mn);
        m = mn;
    }
    if ((tid & 31) == 0) { sm[tid >> 5] = m; ss[tid >> 5] = s; }
    __syncthreads();
    float M = sm[0], S = ss[0];
    #pragma unroll
    for (int i = 1; i < 8; ++i) {
        float mo = sm[i], so = ss[i];
        float mn = fmaxf(M, mo);
        S = S * expf(M - mn) + so * expf(mo - mn);
        M = mn;
    }
    float lse = M + logf(S);
    for (int i = tid; i < V / 4; i += 256) {
        float4 v = r4[i];
        v.x -= lse; v.y -= lse; v.z -= lse; v.w -= lse;
        ((float4*)row)[i] = v;
    }
}

// ---------------- launch ----------------
extern "C" void kernel_launch(void* const* d_in, const int* in_sizes, int n_in,
                              void* d_out, int out_size)
{
    const int*   X   = (const int*)d_in[0];
    const float* Wxf = (const float*)d_in[1];
    const float* Whf = (const float*)d_in[2];
    const float* Wxi = (const float*)d_in[3];
    const float* Whi = (const float*)d_in[4];
    const float* Wxc = (const float*)d_in[5];
    const float* Whc = (const float*)d_in[6];
    const float* Wxo = (const float*)d_in[7];
    const float* Who = (const float*)d_in[8];
    const float* LW  = (const float*)d_in[9];
    const float* bf  = (const float*)d_in[10];
    const float* bi  = (const float*)d_in[11];
    const float* bc  = (const float*)d_in[12];
    const float* bo  = (const float*)d_in[13];
    const float* LB  = (const float*)d_in[14];

    float* out = (float*)d_out;                     // (T, V) log-softmax
    float* hid = out + (size_t)T * V;               // (1, T, D) hidden states

    gather_kernel<<<T, 256>>>(X, Wxf, Wxi, Wxc, Wxo, bf, bi, bc, bo);
    cvt_kernel<<<(int)(((size_t)V * D / 4) / 256), 256>>>(LW);
    lstm_kernel<<<NB, 256>>>(Whf, Whi, Whc, Who, hid);
    dim3 gg(V / 128, T / 128);
    gemm_kernel<<<gg, 256>>>(LB, out);
    logsoftmax_kernel<<<T, 256>>>(out);
}

// round 14
// speedup vs baseline: 1.0395x; 1.0395x over previous
#include <cuda_runtime.h>
#include <cuda_bf16.h>
#include <cstdint>
#include <math.h>

#define D  1024
#define T  2048
#define V  32000
#define NB 128     // persistent CTAs, 1 per SM (128 <= 148)
#define JT 8       // hidden units owned per CTA (NB*JT == D)

// ---------------- device scratch (no allocs allowed) ----------------
__device__ __align__(16) float g_xpre[(size_t)T * 4 * D];    // 32 MB x-contrib + bias
// tagged hidden state, double-buffered by step parity: {tag:32 | h_bits:32}
__device__ __align__(16) unsigned long long g_hpk[2][D];
__device__ __align__(16) __nv_bfloat16 g_Hbf[(size_t)T * D]; // 4 MB bf16 hidden states
__device__ __align__(16) __nv_bfloat16 g_Wbf[(size_t)V * D]; // 64 MB bf16 linear weight

// fast sigmoid / tanh via ex2.approx + rcp.approx (rel err ~1e-6)
__device__ __forceinline__ float fast_sigmoid(float x) {
    return __fdividef(1.f, 1.f + __expf(-x));
}
__device__ __forceinline__ float fast_tanh(float x) {
    return fmaf(2.f, __fdividef(1.f, 1.f + __expf(-2.f * x)), -1.f);
}

// ---------------- kernel 1: gather x-projections, reset state ----------------
__global__ void __launch_bounds__(256) gather_kernel(
    const int* __restrict__ X32,
    const float* __restrict__ Wxf, const float* __restrict__ Wxi,
    const float* __restrict__ Wxc, const float* __restrict__ Wxo,
    const float* __restrict__ bf,  const float* __restrict__ bi,
    const float* __restrict__ bc,  const float* __restrict__ bo)
{
    int t   = blockIdx.x;
    int tid = threadIdx.x;

    // int64 vs int32 ids: little-endian int64 ids < 32000 -> odd words zero.
    int pred = 0;
    if (tid < 64) {
        int p = (tid * 37) & 1023;
        pred = (X32[2 * p + 1] != 0);
    }
    int any_nonzero = __syncthreads_or(pred);
    int id = any_nonzero ? X32[t] : X32[2 * t];

    if (t == 0) {
        // h^0 = 0 with tag 0 in slot 0; slot 1 tag 0 (!= any wanted odd tag)
        #pragma unroll
        for (int q = 0; q < 4; ++q) {
            g_hpk[0][tid * 4 + q] = 0ull;
            g_hpk[1][tid * 4 + q] = 0ull;
        }
    }

    const float* Wx[4] = {Wxf, Wxi, Wxc, Wxo};
    const float* bs[4] = {bf,  bi,  bc,  bo};
    size_t rowoff = (size_t)id * D;
    int j = tid * 4;
    #pragma unroll
    for (int g = 0; g < 4; ++g) {
        float4 v = *(const float4*)(Wx[g] + rowoff + j);
        float4 b = *(const float4*)(bs[g] + j);
        v.x += b.x; v.y += b.y; v.z += b.z; v.w += b.w;
        *(float4*)(g_xpre + ((size_t)t * 4 + g) * D + j) = v;
    }
}

// ---------------- kernel 1b: convert linear_weight to bf16 ----------------
__global__ void __launch_bounds__(256) cvt_kernel(const float* __restrict__ W)
{
    size_t i = (size_t)blockIdx.x * 256 + threadIdx.x;   // float4 index
    float4 v = ((const float4*)W)[i];
    __nv_bfloat162* o = (__nv_bfloat162*)g_Wbf + i * 2;
    o[0] = __floats2bfloat162_rn(v.x, v.y);
    o[1] = __floats2bfloat162_rn(v.z, v.w);
}

// ---------------- kernel 2: persistent LSTM, weights in registers ----------
// 128 CTAs x 256 threads, 1 CTA/SM. Thread (warp w, lane) holds
// W[gate(lane>>3)][k in 128w..128(w+1))][j = 8*cta + (lane&7)] in 128 regs.
// Sync: tagged 8B words {step+1, h_bits}; each warp polls exactly its own
// k-segment (warp-local exchange -> __syncwarp, no CTA barrier before FMA).
__global__ void __launch_bounds__(256, 1) lstm_kernel(
    const float* __restrict__ Whf, const float* __restrict__ Whi,
    const float* __restrict__ Whc, const float* __restrict__ Who,
    float* __restrict__ hid_out)
{
    __shared__ float sh_h[D];
    __shared__ float sh_ps[8][33];

    int tid   = threadIdx.x;
    int w     = tid >> 5;
    int lane  = tid & 31;
    int g     = lane >> 3;
    int jj    = lane & 7;
    int jbase = blockIdx.x * JT;
    int j     = jbase + jj;

    const float* Wm = (g == 0) ? Whf : (g == 1) ? Whi : (g == 2) ? Whc : Who;
    float wreg[128];
    #pragma unroll
    for (int kk = 0; kk < 128; ++kk)
        wreg[kk] = Wm[(size_t)(w * 128 + kk) * D + j];

    float c = 0.f;   // cell state: lives in warp-0 lanes 0..7

    for (int t = 0; t < T; ++t) {
        // x-contribution (DRAM streaming; issued early, consumed after reduce)
        float xv = 0.f;
        if (w == 0) xv = __ldcs(&g_xpre[((size_t)t * 4 + g) * D + j]);

        // acquire h^t: poll own 4 tagged words with two 16B volatile loads
        {
            const unsigned long long* hp = &g_hpk[t & 1][tid * 4];
            unsigned tag = (unsigned)t;
            unsigned long long v0, v1, v2, v3;
            for (;;) {
                asm volatile("ld.volatile.global.v2.u64 {%0,%1}, [%2];"
                             : "=l"(v0), "=l"(v1) : "l"(hp));
                asm volatile("ld.volatile.global.v2.u64 {%0,%1}, [%2];"
                             : "=l"(v2), "=l"(v3) : "l"(hp + 2));
                if ((unsigned)(v0 >> 32) == tag && (unsigned)(v1 >> 32) == tag &&
                    (unsigned)(v2 >> 32) == tag && (unsigned)(v3 >> 32) == tag)
                    break;
            }
            ((float4*)sh_h)[tid] = make_float4(
                __uint_as_float((unsigned)v0), __uint_as_float((unsigned)v1),
                __uint_as_float((unsigned)v2), __uint_as_float((unsigned)v3));
        }
        __syncwarp();     // sh_h exchange is warp-local (thread tid's words
                          // tid*4.. lie exactly in warp w's k-segment)

        float a0 = 0.f, a1 = 0.f, a2 = 0.f, a3 = 0.f;
        const float4* h4 = ((const float4*)sh_h) + w * 32;
        #pragma unroll
        for (int q = 0; q < 32; ++q) {
            float4 hv = h4[q];
            a0 = fmaf(hv.x, wreg[4 * q + 0], a0);
            a1 = fmaf(hv.y, wreg[4 * q + 1], a1);
            a2 = fmaf(hv.z, wreg[4 * q + 2], a2);
            a3 = fmaf(hv.w, wreg[4 * q + 3], a3);
        }
        sh_ps[w][lane] = (a0 + a1) + (a2 + a3);
        __syncthreads();   // (B) sh_ps complete

        if (w == 0) {
            float s = xv +
                ((sh_ps[0][lane] + sh_ps[1][lane]) +
                 (sh_ps[2][lane] + sh_ps[3][lane])) +
                ((sh_ps[4][lane] + sh_ps[5][lane]) +
                 (sh_ps[6][lane] + sh_ps[7][lane]));
            float a = (g == 2) ? fast_tanh(s) : fast_sigmoid(s);
            float fv = __shfl_sync(0xffffffffu, a, jj);
            float iv = __shfl_sync(0xffffffffu, a, 8 + jj);
            float gv = __shfl_sync(0xffffffffu, a, 16 + jj);
            float ov = __shfl_sync(0xffffffffu, a, 24 + jj);
            if (lane < 8) {
                c = fmaf(fv, c, iv * gv);
                float h = fast_tanh(c) * ov;
                // publish FIRST: single aligned 8B store = atomic, self-flagging
                unsigned long long pk =
                    ((unsigned long long)(unsigned)(t + 1) << 32) |
                    (unsigned long long)__float_as_uint(h);
                *(volatile unsigned long long*)&g_hpk[(t + 1) & 1][jbase + lane] = pk;
                // off critical path:
                hid_out[(size_t)t * D + jbase + lane] = h;
                g_Hbf[(size_t)t * D + jbase + lane] = __float2bfloat16(h);
            }
        }
        // no trailing sync: sh_ps writes of step t+1 are ordered by the poll
        // (own CTA publishes t+1 only after warp 0 read sh_ps@t), and sync (B)
        // of t+1 orders them before warp 0's next read.
    }
}

// ---------------- kernel 3: bf16 tensor-core GEMM  C = H @ W^T + bias ----------
// 128x128 block tile, BK=32, 8 warps (2x4), 64x32 warp tile, mma.m16n8k16.bf16.
__global__ void __launch_bounds__(256) gemm_kernel(
    const float* __restrict__ bias,   // (V)
    float* __restrict__ out)          // (T, V)
{
    __shared__ __align__(16) __nv_bfloat16 As[2][128][40];
    __shared__ __align__(16) __nv_bfloat16 Bs[2][128][40];

    int tid  = threadIdx.x;
    int lane = tid & 31;
    int w    = tid >> 5;
    int wm   = w >> 2;
    int wn   = w & 3;
    int t0   = blockIdx.y * 128;
    int v0   = blockIdx.x * 128;

    const __nv_bfloat16* Hbf = g_Hbf;
    const __nv_bfloat16* Wbf = g_Wbf;

    float acc[4][4][4];
    #pragma unroll
    for (int mi = 0; mi < 4; ++mi)
        #pragma unroll
        for (int ni = 0; ni < 4; ++ni)
            #pragma unroll
            for (int q = 0; q < 4; ++q) acc[mi][ni][q] = 0.f;

    #pragma unroll
    for (int s = 0; s < 2; ++s) {
        int f = tid + s * 256, row = f >> 2, q = f & 3;
        *(uint4*)&As[0][row][q * 8] =
            *(const uint4*)(Hbf + (size_t)(t0 + row) * D + q * 8);
        *(uint4*)&Bs[0][row][q * 8] =
            *(const uint4*)(Wbf + (size_t)(v0 + row) * D + q * 8);
    }
    __syncthreads();

    int p = 0;
    for (int kb = 0; kb < 32; ++kb) {
        uint4 ra[2], rb[2];
        if (kb < 31) {
            int d0 = (kb + 1) * 32;
            #pragma unroll
            for (int s = 0; s < 2; ++s) {
                int f = tid + s * 256, row = f >> 2, q = f & 3;
                ra[s] = *(const uint4*)(Hbf + (size_t)(t0 + row) * D + d0 + q * 8);
                rb[s] = *(const uint4*)(Wbf + (size_t)(v0 + row) * D + d0 + q * 8);
            }
        }

        #pragma unroll
        for (int ks = 0; ks < 2; ++ks) {
            int k0 = ks * 16;
            uint32_t af[4][4];
            #pragma unroll
            for (int mi = 0; mi < 4; ++mi) {
                int row = wm * 64 + mi * 16 + (lane & 7) + ((lane >> 3) & 1) * 8;
                int kc  = k0 + (lane >> 4) * 8;
                uint32_t a = (uint32_t)__cvta_generic_to_shared(&As[p][row][kc]);
                asm volatile(
                    "ldmatrix.sync.aligned.m8n8.x4.shared.b16 {%0,%1,%2,%3}, [%4];"
                    : "=r"(af[mi][0]), "=r"(af[mi][1]),
                      "=r"(af[mi][2]), "=r"(af[mi][3]) : "r"(a));
            }
            uint32_t bfr[4][2];
            #pragma unroll
            for (int ni = 0; ni < 4; ++ni) {
                int nrow = wn * 32 + ni * 8 + (lane & 7);
                int kc   = k0 + ((lane >> 3) & 1) * 8;
                uint32_t a = (uint32_t)__cvta_generic_to_shared(&Bs[p][nrow][kc]);
                asm volatile(
                    "ldmatrix.sync.aligned.m8n8.x2.shared.b16 {%0,%1}, [%2];"
                    : "=r"(bfr[ni][0]), "=r"(bfr[ni][1]) : "r"(a));
            }
            #pragma unroll
            for (int mi = 0; mi < 4; ++mi)
                #pragma unroll
                for (int ni = 0; ni < 4; ++ni)
                    asm volatile(
                        "mma.sync.aligned.m16n8k16.row.col.f32.bf16.bf16.f32 "
                        "{%0,%1,%2,%3}, {%4,%5,%6,%7}, {%8,%9}, {%0,%1,%2,%3};"
                        : "+f"(acc[mi][ni][0]), "+f"(acc[mi][ni][1]),
                          "+f"(acc[mi][ni][2]), "+f"(acc[mi][ni][3])
                        : "r"(af[mi][0]), "r"(af[mi][1]),
                          "r"(af[mi][2]), "r"(af[mi][3]),
                          "r"(bfr[ni][0]), "r"(bfr[ni][1]));
        }

        if (kb < 31) {
            #pragma unroll
            for (int s = 0; s < 2; ++s) {
                int f = tid + s * 256, row = f >> 2, q = f & 3;
                *(uint4*)&As[p ^ 1][row][q * 8] = ra[s];
                *(uint4*)&Bs[p ^ 1][row][q * 8] = rb[s];
            }
        }
        __syncthreads();
        p ^= 1;
    }

    int rowA = lane >> 2;
    int colB = (lane & 3) * 2;
    #pragma unroll
    for (int mi = 0; mi < 4; ++mi) {
        int m = t0 + wm * 64 + mi * 16 + rowA;
        #pragma unroll
        for (int ni = 0; ni < 4; ++ni) {
            int n = v0 + wn * 32 + ni * 8 + colB;
            float bx = bias[n], by = bias[n + 1];
            *(float2*)(out + (size_t)m * V + n) =
                make_float2(acc[mi][ni][0] + bx, acc[mi][ni][1] + by);
            *(float2*)(out + (size_t)(m + 8) * V + n) =
                make_float2(acc[mi][ni][2] + bx, acc[mi][ni][3] + by);
        }
    }
}

// ---------------- kernel 4: online single-read log_softmax ----------------
__global__ void __launch_bounds__(256) logsoftmax_kernel(float* __restrict__ out)
{
    size_t t   = blockIdx.x;
    float* row = out + t * (size_t)V;
    int tid = threadIdx.x;
    __shared__ float sm[8], ss[8];

    float m = -INFINITY, s = 0.f;
    const float4* r4 = (const float4*)row;
    for (int i = tid; i < V / 4; i += 256) {
        float4 v = r4[i];
        float mx = fmaxf(fmaxf(v.x, v.y), fmaxf(v.z, v.w));
        if (mx > m) { s *= expf(m - mx); m = mx; }
        s += expf(v.x - m) + expf(v.y - m) + expf(v.z - m) + expf(v.w - m);
    }
    #pragma unroll
    for (int o = 16; o; o >>= 1) {
        float mo = __shfl_xor_sync(0xffffffffu, m, o);
        float so = __shfl_xor_sync(0xffffffffu, s, o);
        float mn = fmaxf(m, mo);
        s = s * expf(m - mn) + so * expf(mo - mn);
        m = mn;
    }
    if ((tid & 31) == 0) { sm[tid >> 5] = m; ss[tid >> 5] = s; }
    __syncthreads();
    float M = sm[0], S = ss[0];
    #pragma unroll
    for (int i = 1; i < 8; ++i) {
        float mo = sm[i], so = ss[i];
        float mn = fmaxf(M, mo);
        S = S * expf(M - mn) + so * expf(mo - mn);
        M = mn;
    }
    float lse = M + logf(S);
    for (int i = tid; i < V / 4; i += 256) {
        float4 v = r4[i];
        v.x -= lse; v.y -= lse; v.z -= lse; v.w -= lse;
        ((float4*)row)[i] = v;
    }
}

// ---------------- launch ----------------
extern "C" void kernel_launch(void* const* d_in, const int* in_sizes, int n_in,
                              void* d_out, int out_size)
{
    const int*   X   = (const int*)d_in[0];
    const float* Wxf = (const float*)d_in[1];
    const float* Whf = (const float*)d_in[2];
    const float* Wxi = (const float*)d_in[3];
    const float* Whi = (const float*)d_in[4];
    const float* Wxc = (const float*)d_in[5];
    const float* Whc = (const float*)d_in[6];
    const float* Wxo = (const float*)d_in[7];
    const float* Who = (const float*)d_in[8];
    const float* LW  = (const float*)d_in[9];
    const float* bf  = (const float*)d_in[10];
    const float* bi  = (const float*)d_in[11];
    const float* bc  = (const float*)d_in[12];
    const float* bo  = (const float*)d_in[13];
    const float* LB  = (const float*)d_in[14];

    float* out = (float*)d_out;                     // (T, V) log-softmax
    float* hid = out + (size_t)T * V;               // (1, T, D) hidden states

    gather_kernel<<<T, 256>>>(X, Wxf, Wxi, Wxc, Wxo, bf, bi, bc, bo);
    cvt_kernel<<<(int)(((size_t)V * D / 4) / 256), 256>>>(LW);
    lstm_kernel<<<NB, 256>>>(Whf, Whi, Whc, Who, hid);
    dim3 gg(V / 128, T / 128);
    gemm_kernel<<<gg, 256>>>(LB, out);
    logsoftmax_kernel<<<T, 256>>>(out);
}

// round 15
// speedup vs baseline: 1.0474x; 1.0076x over previous
#include <cuda_runtime.h>
#include <cuda_bf16.h>
#include <cstdint>
#include <math.h>

#define D  1024
#define T  2048
#define V  32000
#define NB 128     // persistent CTAs, 1 per SM (128 <= 148)
#define JT 8       // hidden units owned per CTA (NB*JT == D)

// ---------------- device scratch (no allocs allowed) ----------------
__device__ __align__(16) float g_xpre[(size_t)T * 4 * D];    // 32 MB x-contrib + bias
// tagged hidden state, double-buffered by step parity: {tag:32 | h_bits:32}
__device__ __align__(16) unsigned long long g_hpk[2][D];
__device__ __align__(16) __nv_bfloat16 g_Hbf[(size_t)T * D]; // 4 MB bf16 hidden states
__device__ __align__(16) __nv_bfloat16 g_Wbf[(size_t)V * D]; // 64 MB bf16 linear weight

// fast sigmoid / tanh via ex2.approx + rcp.approx (rel err ~1e-6)
__device__ __forceinline__ float fast_sigmoid(float x) {
    return __fdividef(1.f, 1.f + __expf(-x));
}
__device__ __forceinline__ float fast_tanh(float x) {
    return fmaf(2.f, __fdividef(1.f, 1.f + __expf(-2.f * x)), -1.f);
}

// ---------------- kernel 1: gather x-projections, reset state ----------------
__global__ void __launch_bounds__(256) gather_kernel(
    const int* __restrict__ X32,
    const float* __restrict__ Wxf, const float* __restrict__ Wxi,
    const float* __restrict__ Wxc, const float* __restrict__ Wxo,
    const float* __restrict__ bf,  const float* __restrict__ bi,
    const float* __restrict__ bc,  const float* __restrict__ bo)
{
    int t   = blockIdx.x;
    int tid = threadIdx.x;

    // int64 vs int32 ids: little-endian int64 ids < 32000 -> odd words zero.
    int pred = 0;
    if (tid < 64) {
        int p = (tid * 37) & 1023;
        pred = (X32[2 * p + 1] != 0);
    }
    int any_nonzero = __syncthreads_or(pred);
    int id = any_nonzero ? X32[t] : X32[2 * t];

    if (t == 0) {
        // h^0 = 0 with tag 0 in slot 0; slot 1 tag 0 (!= any wanted tag)
        #pragma unroll
        for (int q = 0; q < 4; ++q) {
            g_hpk[0][tid * 4 + q] = 0ull;
            g_hpk[1][tid * 4 + q] = 0ull;
        }
    }

    const float* Wx[4] = {Wxf, Wxi, Wxc, Wxo};
    const float* bs[4] = {bf,  bi,  bc,  bo};
    size_t rowoff = (size_t)id * D;
    int j = tid * 4;
    #pragma unroll
    for (int g = 0; g < 4; ++g) {
        float4 v = *(const float4*)(Wx[g] + rowoff + j);
        float4 b = *(const float4*)(bs[g] + j);
        v.x += b.x; v.y += b.y; v.z += b.z; v.w += b.w;
        *(float4*)(g_xpre + ((size_t)t * 4 + g) * D + j) = v;
    }
}

// ---------------- kernel 1b: convert linear_weight to bf16 ----------------
__global__ void __launch_bounds__(256) cvt_kernel(const float* __restrict__ W)
{
    size_t i = (size_t)blockIdx.x * 256 + threadIdx.x;   // float4 index
    float4 v = ((const float4*)W)[i];
    __nv_bfloat162* o = (__nv_bfloat162*)g_Wbf + i * 2;
    o[0] = __floats2bfloat162_rn(v.x, v.y);
    o[1] = __floats2bfloat162_rn(v.z, v.w);
}

// ---------------- kernel 2: persistent LSTM, weights in registers ----------
// 128 CTAs x 256 threads, 1 CTA/SM. Thread (warp w, lane) holds
// W[gate(lane>>3)][k in 128w..128(w+1))][j = 8*cta + (lane&7)] in 128 regs.
// Sync: tagged 8B words {step+1, h_bits}; each warp polls exactly its own
// k-segment. x-contribution double-buffered in a register: the DRAM load for
// step t+1 is issued at the top of step t, removing DRAM latency variance
// from warp 0's serial tail (the chip-wide critical path).
__global__ void __launch_bounds__(256, 1) lstm_kernel(
    const float* __restrict__ Whf, const float* __restrict__ Whi,
    const float* __restrict__ Whc, const float* __restrict__ Who,
    float* __restrict__ hid_out)
{
    __shared__ float sh_h[D];
    __shared__ float sh_ps[8][33];

    int tid   = threadIdx.x;
    int w     = tid >> 5;
    int lane  = tid & 31;
    int g     = lane >> 3;
    int jj    = lane & 7;
    int jbase = blockIdx.x * JT;
    int j     = jbase + jj;

    const float* Wm = (g == 0) ? Whf : (g == 1) ? Whi : (g == 2) ? Whc : Who;
    float wreg[128];
    #pragma unroll
    for (int kk = 0; kk < 128; ++kk)
        wreg[kk] = Wm[(size_t)(w * 128 + kk) * D + j];

    float c = 0.f;   // cell state: lives in warp-0 lanes 0..7

    // prologue: x-contribution for step 0
    float xv = 0.f;
    if (w == 0) xv = __ldcs(&g_xpre[(size_t)g * D + j]);

    for (int t = 0; t < T; ++t) {
        // prefetch x-contribution for step t+1 (consumed next iteration's tail
        // -> ~one full step of latency cover, DRAM variance off critical path)
        float xv_next = 0.f;
        if (w == 0) {
            int tn = (t + 1 < T) ? t + 1 : T - 1;
            xv_next = __ldcs(&g_xpre[((size_t)tn * 4 + g) * D + j]);
        }

        // acquire h^t: poll own 4 tagged words with two 16B volatile loads
        {
            const unsigned long long* hp = &g_hpk[t & 1][tid * 4];
            unsigned tag = (unsigned)t;
            unsigned long long v0, v1, v2, v3;
            for (;;) {
                asm volatile("ld.volatile.global.v2.u64 {%0,%1}, [%2];"
                             : "=l"(v0), "=l"(v1) : "l"(hp));
                asm volatile("ld.volatile.global.v2.u64 {%0,%1}, [%2];"
                             : "=l"(v2), "=l"(v3) : "l"(hp + 2));
                if ((unsigned)(v0 >> 32) == tag && (unsigned)(v1 >> 32) == tag &&
                    (unsigned)(v2 >> 32) == tag && (unsigned)(v3 >> 32) == tag)
                    break;
            }
            ((float4*)sh_h)[tid] = make_float4(
                __uint_as_float((unsigned)v0), __uint_as_float((unsigned)v1),
                __uint_as_float((unsigned)v2), __uint_as_float((unsigned)v3));
        }
        __syncwarp();     // sh_h exchange is warp-local

        float a0 = 0.f, a1 = 0.f, a2 = 0.f, a3 = 0.f;
        const float4* h4 = ((const float4*)sh_h) + w * 32;
        #pragma unroll
        for (int q = 0; q < 32; ++q) {
            float4 hv = h4[q];
            a0 = fmaf(hv.x, wreg[4 * q + 0], a0);
            a1 = fmaf(hv.y, wreg[4 * q + 1], a1);
            a2 = fmaf(hv.z, wreg[4 * q + 2], a2);
            a3 = fmaf(hv.w, wreg[4 * q + 3], a3);
        }
        sh_ps[w][lane] = (a0 + a1) + (a2 + a3);
        __syncthreads();   // (B) sh_ps complete

        if (w == 0) {
            float s = xv +
                ((sh_ps[0][lane] + sh_ps[1][lane]) +
                 (sh_ps[2][lane] + sh_ps[3][lane])) +
                ((sh_ps[4][lane] + sh_ps[5][lane]) +
                 (sh_ps[6][lane] + sh_ps[7][lane]));
            float a = (g == 2) ? fast_tanh(s) : fast_sigmoid(s);
            float fv = __shfl_sync(0xffffffffu, a, jj);
            float iv = __shfl_sync(0xffffffffu, a, 8 + jj);
            float gv = __shfl_sync(0xffffffffu, a, 16 + jj);
            float ov = __shfl_sync(0xffffffffu, a, 24 + jj);
            if (lane < 8) {
                c = fmaf(fv, c, iv * gv);
                float h = fast_tanh(c) * ov;
                // publish FIRST: single aligned 8B store = atomic, self-flagging
                unsigned long long pk =
                    ((unsigned long long)(unsigned)(t + 1) << 32) |
                    (unsigned long long)__float_as_uint(h);
                *(volatile unsigned long long*)&g_hpk[(t + 1) & 1][jbase + lane] = pk;
                // off critical path:
                hid_out[(size_t)t * D + jbase + lane] = h;
                g_Hbf[(size_t)t * D + jbase + lane] = __float2bfloat16(h);
            }
        }
        xv = xv_next;
        // no trailing sync: sh_ps writes of step t+1 are ordered by the poll,
        // and sync (B) of t+1 orders them before warp 0's next read.
    }
}

// ---------------- kernel 3: bf16 tensor-core GEMM  C = H @ W^T + bias ----------
// 256x128 block tile, BK=32 double-buffered, 8 warps (4x2), 64x64 warp tile.
// All fragment loads via ldmatrix.x4 (B pairs fused). Dynamic smem 61,440 B.
__global__ void __launch_bounds__(256, 1) gemm_kernel(
    const float* __restrict__ bias,   // (V)
    float* __restrict__ out)          // (T, V)
{
    extern __shared__ __align__(16) __nv_bfloat16 smem[];
    // As: [2][256][40] at offset 0 ; Bs: [2][128][40] at offset 20480 elems
    __nv_bfloat16* As = smem;
    __nv_bfloat16* Bs = smem + 2 * 256 * 40;

    int tid  = threadIdx.x;
    int lane = tid & 31;
    int w    = tid >> 5;
    int wm   = w >> 1;          // 0..3 -> m offset 64*wm
    int wn   = w & 1;           // 0..1 -> n offset 64*wn
    int t0   = blockIdx.y * 256;
    int v0   = blockIdx.x * 128;

    const __nv_bfloat16* Hbf = g_Hbf;
    const __nv_bfloat16* Wbf = g_Wbf;

    float acc[4][8][4];
    #pragma unroll
    for (int mi = 0; mi < 4; ++mi)
        #pragma unroll
        for (int ni = 0; ni < 8; ++ni)
            #pragma unroll
            for (int q = 0; q < 4; ++q) acc[mi][ni][q] = 0.f;

    // initial tile (kb = 0)
    #pragma unroll
    for (int s = 0; s < 4; ++s) {               // A: 1024 uint4 chunks
        int f = tid + s * 256, row = f >> 2, q = f & 3;
        *(uint4*)&As[(size_t)row * 40 + q * 8] =
            *(const uint4*)(Hbf + (size_t)(t0 + row) * D + q * 8);
    }
    #pragma unroll
    for (int s = 0; s < 2; ++s) {               // B: 512 uint4 chunks
        int f = tid + s * 256, row = f >> 2, q = f & 3;
        *(uint4*)&Bs[(size_t)row * 40 + q * 8] =
            *(const uint4*)(Wbf + (size_t)(v0 + row) * D + q * 8);
    }
    __syncthreads();

    int p = 0;
    for (int kb = 0; kb < 32; ++kb) {
        uint4 ra[4], rb[2];
        if (kb < 31) {
            int d0 = (kb + 1) * 32;
            #pragma unroll
            for (int s = 0; s < 4; ++s) {
                int f = tid + s * 256, row = f >> 2, q = f & 3;
                ra[s] = *(const uint4*)(Hbf + (size_t)(t0 + row) * D + d0 + q * 8);
            }
            #pragma unroll
            for (int s = 0; s < 2; ++s) {
                int f = tid + s * 256, row = f >> 2, q = f & 3;
                rb[s] = *(const uint4*)(Wbf + (size_t)(v0 + row) * D + d0 + q * 8);
            }
        }

        const __nv_bfloat16* Ap = As + (size_t)p * 256 * 40;
        const __nv_bfloat16* Bp = Bs + (size_t)p * 128 * 40;

        #pragma unroll
        for (int ks = 0; ks < 2; ++ks) {
            int k0 = ks * 16;
            uint32_t af[4][4];
            #pragma unroll
            for (int mi = 0; mi < 4; ++mi) {
                int row = wm * 64 + mi * 16 + (lane & 7) + ((lane >> 3) & 1) * 8;
                int kc  = k0 + (lane >> 4) * 8;
                uint32_t a = (uint32_t)__cvta_generic_to_shared(
                    &Ap[(size_t)row * 40 + kc]);
                asm volatile(
                    "ldmatrix.sync.aligned.m8n8.x4.shared.b16 {%0,%1,%2,%3}, [%4];"
                    : "=r"(af[mi][0]), "=r"(af[mi][1]),
                      "=r"(af[mi][2]), "=r"(af[mi][3]) : "r"(a));
            }
            uint32_t bfr[8][2];
            #pragma unroll
            for (int nj = 0; nj < 4; ++nj) {
                // x4 covering ni = 2nj (mats 0,1) and ni = 2nj+1 (mats 2,3)
                int nrow = wn * 64 + nj * 16 + ((lane >> 4) & 1) * 8 + (lane & 7);
                int kc   = k0 + ((lane >> 3) & 1) * 8;
                uint32_t a = (uint32_t)__cvta_generic_to_shared(
                    &Bp[(size_t)nrow * 40 + kc]);
                asm volatile(
                    "ldmatrix.sync.aligned.m8n8.x4.shared.b16 {%0,%1,%2,%3}, [%4];"
                    : "=r"(bfr[2 * nj][0]), "=r"(bfr[2 * nj][1]),
                      "=r"(bfr[2 * nj + 1][0]), "=r"(bfr[2 * nj + 1][1]) : "r"(a));
            }
            #pragma unroll
            for (int mi = 0; mi < 4; ++mi)
                #pragma unroll
                for (int ni = 0; ni < 8; ++ni)
                    asm volatile(
                        "mma.sync.aligned.m16n8k16.row.col.f32.bf16.bf16.f32 "
                        "{%0,%1,%2,%3}, {%4,%5,%6,%7}, {%8,%9}, {%0,%1,%2,%3};"
                        : "+f"(acc[mi][ni][0]), "+f"(acc[mi][ni][1]),
                          "+f"(acc[mi][ni][2]), "+f"(acc[mi][ni][3])
                        : "r"(af[mi][0]), "r"(af[mi][1]),
                          "r"(af[mi][2]), "r"(af[mi][3]),
                          "r"(bfr[ni][0]), "r"(bfr[ni][1]));
        }

        if (kb < 31) {
            __nv_bfloat16* An = As + (size_t)(p ^ 1) * 256 * 40;
            __nv_bfloat16* Bn = Bs + (size_t)(p ^ 1) * 128 * 40;
            #pragma unroll
            for (int s = 0; s < 4; ++s) {
                int f = tid + s * 256, row = f >> 2, q = f & 3;
                *(uint4*)&An[(size_t)row * 40 + q * 8] = ra[s];
            }
            #pragma unroll
            for (int s = 0; s < 2; ++s) {
                int f = tid + s * 256, row = f >> 2, q = f & 3;
                *(uint4*)&Bn[(size_t)row * 40 + q * 8] = rb[s];
            }
        }
        __syncthreads();
        p ^= 1;
    }

    // epilogue: add bias, write fp32
    int rowA = lane >> 2;
    int colB = (lane & 3) * 2;
    #pragma unroll
    for (int mi = 0; mi < 4; ++mi) {
        int m = t0 + wm * 64 + mi * 16 + rowA;
        #pragma unroll
        for (int ni = 0; ni < 8; ++ni) {
            int n = v0 + wn * 64 + ni * 8 + colB;
            float bx = bias[n], by = bias[n + 1];
            *(float2*)(out + (size_t)m * V + n) =
                make_float2(acc[mi][ni][0] + bx, acc[mi][ni][1] + by);
            *(float2*)(out + (size_t)(m + 8) * V + n) =
                make_float2(acc[mi][ni][2] + bx, acc[mi][ni][3] + by);
        }
    }
}

// ---------------- kernel 4: online single-read log_softmax ----------------
__global__ void __launch_bounds__(256) logsoftmax_kernel(float* __restrict__ out)
{
    size_t t   = blockIdx.x;
    float* row = out + t * (size_t)V;
    int tid = threadIdx.x;
    __shared__ float sm[8], ss[8];

    float m = -INFINITY, s = 0.f;
    const float4* r4 = (const float4*)row;
    for (int i = tid; i < V / 4; i += 256) {
        float4 v = r4[i];
        float mx = fmaxf(fmaxf(v.x, v.y), fmaxf(v.z, v.w));
        if (mx > m) { s *= expf(m - mx); m = mx; }
        s += expf(v.x - m) + expf(v.y - m) + expf(v.z - m) + expf(v.w - m);
    }
    #pragma unroll
    for (int o = 16; o; o >>= 1) {
        float mo = __shfl_xor_sync(0xffffffffu, m, o);
        float so = __shfl_xor_sync(0xffffffffu, s, o);
        float mn = fmaxf(m, mo);
        s = s * expf(m - mn) + so * expf(mo - mn);
        m = mn;
    }
    if ((tid & 31) == 0) { sm[tid >> 5] = m; ss[tid >> 5] = s; }
    __syncthreads();
    float M = sm[0], S = ss[0];
    #pragma unroll
    for (int i = 1; i < 8; ++i) {
        float mo = sm[i], so = ss[i];
        float mn = fmaxf(M, mo);
        S = S * expf(M - mn) + so * expf(mo - mn);
        M = mn;
    }
    float lse = M + logf(S);
    for (int i = tid; i < V / 4; i += 256) {
        float4 v = r4[i];
        v.x -= lse; v.y -= lse; v.z -= lse; v.w -= lse;
        ((float4*)row)[i] = v;
    }
}

// ---------------- launch ----------------
extern "C" void kernel_launch(void* const* d_in, const int* in_sizes, int n_in,
                              void* d_out, int out_size)
{
    const int*   X   = (const int*)d_in[0];
    const float* Wxf = (const float*)d_in[1];
    const float* Whf = (const float*)d_in[2];
    const float* Wxi = (const float*)d_in[3];
    const float* Whi = (const float*)d_in[4];
    const float* Wxc = (const float*)d_in[5];
    const float* Whc = (const float*)d_in[6];
    const float* Wxo = (const float*)d_in[7];
    const float* Who = (const float*)d_in[8];
    const float* LW  = (const float*)d_in[9];
    const float* bf  = (const float*)d_in[10];
    const float* bi  = (const float*)d_in[11];
    const float* bc  = (const float*)d_in[12];
    const float* bo  = (const float*)d_in[13];
    const float* LB  = (const float*)d_in[14];

    float* out = (float*)d_out;                     // (T, V) log-softmax
    float* hid = out + (size_t)T * V;               // (1, T, D) hidden states

    const int GEMM_SMEM = (2 * 256 * 40 + 2 * 128 * 40) * 2;  // 61440 B
    cudaFuncSetAttribute(gemm_kernel,
                         cudaFuncAttributeMaxDynamicSharedMemorySize, GEMM_SMEM);

    gather_kernel<<<T, 256>>>(X, Wxf, Wxi, Wxc, Wxo, bf, bi, bc, bo);
    cvt_kernel<<<(int)(((size_t)V * D / 4) / 256), 256>>>(LW);
    lstm_kernel<<<NB, 256>>>(Whf, Whi, Whc, Who, hid);
    dim3 gg(V / 128, T / 256);
    gemm_kernel<<<gg, 256, GEMM_SMEM>>>(LB, out);
    logsoftmax_kernel<<<T, 256>>>(out);
}